// round 1
// baseline (speedup 1.0000x reference)
#include <cuda_runtime.h>
#include <cstdint>

#define B    64
#define HDIM 1024
#define SDIM 2048
#define VDIM 23262
#define EDIM 300
#define G4   4096          // 4*H
#define KCAT (HDIM + EDIM) // 1324

// ---------------- scratch (static device globals; no allocation) ----------------
__device__ float g_q[B * HDIM];
__device__ float g_pm[B * 64];
__device__ float g_pl[B * 64];
__device__ float g_pacc[(size_t)B * 64 * HDIM];   // 16.8 MB attention partials
__device__ float g_catA[B * 2 * HDIM];            // [context | h0]
__device__ float g_catB[B * KCAT];                // [ctx_hat | embedded]
__device__ float g_gates[B * G4];
__device__ float g_hN[B * HDIM];
__device__ float g_part[(size_t)16 * B * G4];     // 16.8 MB split-K partials

// ---------------- packed f32x2 helpers ----------------
__device__ __forceinline__ void ffma2(unsigned long long& d,
                                      unsigned long long a,
                                      unsigned long long w) {
    asm("fma.rn.f32x2 %0, %1, %2, %0;" : "+l"(d) : "l"(a), "l"(w));
}
__device__ __forceinline__ unsigned long long pack_dup(float x) {
    unsigned long long r;
    asm("mov.b64 %0, {%1, %1};" : "=l"(r) : "f"(x));
    return r;
}
__device__ __forceinline__ float2 unpack2(unsigned long long v) {
    float2 r;
    asm("mov.b64 {%0, %1}, %2;" : "=f"(r.x), "=f"(r.y) : "l"(v));
    return r;
}

// ---------------- embedding gather into catB[:, H:H+E] ----------------
__global__ void k_embed(const int* __restrict__ tokens, const float* __restrict__ emb) {
    int b = blockIdx.x;
    int t = tokens[b];
    for (int e = threadIdx.x; e < EDIM; e += blockDim.x)
        g_catB[b * KCAT + HDIM + e] = emb[(size_t)t * EDIM + e];
}

// ---------------- generic skinny GEMM: C[b,n] = sum_k A[b,k] * W(n,k) ----------------
// A is [64, K] row-major. WKMAJOR: W stored [N,K] (row n contiguous in k);
// else W stored [K,N] (row k contiguous in n).
// DIRECT: write C[b*ldc+n] (+bias). else: write split-K partial to
// C[((slice_base+by)*64 + b)*N + n].
template <bool WKMAJOR, bool DIRECT>
__global__ __launch_bounds__(256) void k_gemm(
    const float* __restrict__ A, int lda,
    const float* __restrict__ W, int ldw,
    float* __restrict__ C, int ldc,
    int N, int K, int nsl, int slice_base,
    const float* __restrict__ bias)
{
    __shared__ float sA[32][64];
    __shared__ float sW[32][128];
    int tid = threadIdx.x;
    int tx = tid & 15, ty = tid >> 4;
    int n0 = blockIdx.x * 128;

    int nk32 = (K + 31) >> 5;
    int per  = (nk32 + nsl - 1) / nsl;
    int k0s  = blockIdx.y * per * 32;
    int k0e  = min(K, (int)(blockIdx.y + 1) * per * 32);

    unsigned long long acc[16];
#pragma unroll
    for (int i = 0; i < 16; i++) acc[i] = 0ULL;

    for (int k0 = k0s; k0 < k0e; k0 += 32) {
        // --- load A tile [64b x 32k], store transposed sA[k][b] ---
        {
            int bb = tid >> 2;
            int kk = (tid & 3) << 3;
#pragma unroll
            for (int j = 0; j < 8; j++) {
                int k = k0 + kk + j;
                sA[kk + j][bb] = (k < K) ? A[(size_t)bb * lda + k] : 0.f;
            }
        }
        // --- load W tile [128n x 32k] into sW[k][n] ---
        if (WKMAJOR) {
            int n  = tid >> 1;
            int kk = (tid & 1) << 4;
            bool nv = (n0 + n) < N;
            const float* wp = W + (size_t)(n0 + n) * ldw;
#pragma unroll
            for (int j = 0; j < 16; j++) {
                int k = k0 + kk + j;
                sW[kk + j][n] = (nv && k < K) ? wp[k] : 0.f;
            }
        } else {
            int kk = tid >> 3;
            int nn = (tid & 7) << 4;
            int k  = k0 + kk;
            bool kv = k < K;
            const float* wp = W + (size_t)k * ldw + n0;
#pragma unroll
            for (int j = 0; j < 16; j++) {
                int n = nn + j;
                sW[kk][n] = (kv && (n0 + n) < N) ? wp[n] : 0.f;
            }
        }
        __syncthreads();

#pragma unroll 8
        for (int kk = 0; kk < 32; kk++) {
            float4 a = *(const float4*)&sA[kk][ty * 4];
            unsigned long long a2[4];
            a2[0] = pack_dup(a.x); a2[1] = pack_dup(a.y);
            a2[2] = pack_dup(a.z); a2[3] = pack_dup(a.w);
            const unsigned long long* w2 = (const unsigned long long*)&sW[kk][tx * 8];
            unsigned long long wv0 = w2[0], wv1 = w2[1], wv2 = w2[2], wv3 = w2[3];
#pragma unroll
            for (int bi = 0; bi < 4; bi++) {
                ffma2(acc[bi * 4 + 0], a2[bi], wv0);
                ffma2(acc[bi * 4 + 1], a2[bi], wv1);
                ffma2(acc[bi * 4 + 2], a2[bi], wv2);
                ffma2(acc[bi * 4 + 3], a2[bi], wv3);
            }
        }
        __syncthreads();
    }

    // --- epilogue ---
#pragma unroll
    for (int bi = 0; bi < 4; bi++) {
        int bb = ty * 4 + bi;
#pragma unroll
        for (int j = 0; j < 4; j++) {
            float2 v = unpack2(acc[bi * 4 + j]);
            int n = n0 + tx * 8 + j * 2;
            if (DIRECT) {
                if (n < N)     C[(size_t)bb * ldc + n]     = v.x + (bias ? bias[n] : 0.f);
                if (n + 1 < N) C[(size_t)bb * ldc + n + 1] = v.y + (bias ? bias[n + 1] : 0.f);
            } else {
                size_t base = ((size_t)(slice_base + blockIdx.y) * B + bb) * (size_t)N;
                if (n < N)     C[base + n]     = v.x;
                if (n + 1 < N) C[base + n + 1] = v.y;
            }
        }
    }
}

// ---------------- split-K combine (+bias, +optional tanh) ----------------
__global__ void k_scomb(const float* __restrict__ part, int N, int nsl,
                        const float* __restrict__ b1, const float* __restrict__ b2,
                        int act, float* __restrict__ dst, int ldd)
{
    int idx = blockIdx.x * blockDim.x + threadIdx.x;
    if (idx >= B * N) return;
    int b = idx / N, n = idx % N;
    float v = 0.f;
    if (b1) v += b1[n];
    if (b2) v += b2[n];
    for (int s = 0; s < nsl; s++) v += part[((size_t)s * B + b) * (size_t)N + n];
    if (act) v = tanhf(v);
    dst[(size_t)b * ldd + n] = v;
}

// ---------------- fused attention pass (single read of encoder_out) ----------------
// grid (8, B), 256 threads. Warp wg = bx*8+warp handles 32 consecutive s rows of
// batch b; per-warp online softmax with distributed acc (32 floats/lane).
__global__ __launch_bounds__(256) void k_attn(const float* __restrict__ enc)
{
    int b = blockIdx.y;
    int warp = threadIdx.x >> 5, lane = threadIdx.x & 31;
    int wg = blockIdx.x * 8 + warp;   // 0..63

    const float4* qp = (const float4*)(g_q + (size_t)b * HDIM);
    float4 qv[8];
#pragma unroll
    for (int j = 0; j < 8; j++) qv[j] = qp[j * 32 + lane];

    float4 av[8];
#pragma unroll
    for (int j = 0; j < 8; j++) av[j] = make_float4(0.f, 0.f, 0.f, 0.f);
    float m = -1e30f, l = 0.f;

    int s0 = wg * 32;
    for (int r = 0; r < 32; r++) {
        const float4* row = (const float4*)(enc + ((size_t)(s0 + r) * B + b) * HDIM);
        float4 e[8];
#pragma unroll
        for (int j = 0; j < 8; j++) e[j] = row[j * 32 + lane];
        float d = 0.f;
#pragma unroll
        for (int j = 0; j < 8; j++)
            d += e[j].x * qv[j].x + e[j].y * qv[j].y + e[j].z * qv[j].z + e[j].w * qv[j].w;
#pragma unroll
        for (int off = 16; off > 0; off >>= 1)
            d += __shfl_xor_sync(0xffffffffu, d, off);

        float mn  = fmaxf(m, d);
        float fac = __expf(m - mn);
        float p   = __expf(d - mn);
        l = l * fac + p;
        m = mn;
#pragma unroll
        for (int j = 0; j < 8; j++) {
            av[j].x = av[j].x * fac + p * e[j].x;
            av[j].y = av[j].y * fac + p * e[j].y;
            av[j].z = av[j].z * fac + p * e[j].z;
            av[j].w = av[j].w * fac + p * e[j].w;
        }
    }
    int pi = b * 64 + wg;
    if (lane == 0) { g_pm[pi] = m; g_pl[pi] = l; }
    float4* pa = (float4*)(g_pacc + (size_t)pi * HDIM);
#pragma unroll
    for (int j = 0; j < 8; j++) pa[j * 32 + lane] = av[j];
}

// ---------------- attention combine: context -> catA = [context | h0] ----------------
__global__ void k_attn_comb(const float* __restrict__ h0)
{
    int b = blockIdx.x, t = threadIdx.x;   // 256 threads, 4 h each
    float M = -1e30f;
    for (int c = 0; c < 64; c++) M = fmaxf(M, g_pm[b * 64 + c]);
    float lsum = 0.f;
    float4 ctx = make_float4(0.f, 0.f, 0.f, 0.f);
    for (int c = 0; c < 64; c++) {
        float fac = __expf(g_pm[b * 64 + c] - M);
        lsum += fac * g_pl[b * 64 + c];
        float4 a = *(const float4*)(g_pacc + (size_t)(b * 64 + c) * HDIM + t * 4);
        ctx.x += fac * a.x; ctx.y += fac * a.y;
        ctx.z += fac * a.z; ctx.w += fac * a.w;
    }
    float inv = 1.f / lsum;
    float4* dA = (float4*)(g_catA + (size_t)b * 2 * HDIM);
    dA[t] = make_float4(ctx.x * inv, ctx.y * inv, ctx.z * inv, ctx.w * inv);
    const float4* h4 = (const float4*)(h0 + (size_t)b * HDIM);
    dA[256 + t] = h4[t];
}

// ---------------- LSTM elementwise; writes hN/cN into d_out and g_hN ----------------
__global__ void k_lstm(const float* __restrict__ c0, float* __restrict__ out)
{
    int b = blockIdx.x, t = threadIdx.x;
    const float* g = g_gates + (size_t)b * G4;
#pragma unroll
    for (int c = 0; c < 4; c++) {
        int h = t * 4 + c;
        float gi = g[h], gf = g[HDIM + h], gg = g[2 * HDIM + h], go = g[3 * HDIM + h];
        float si = 1.f / (1.f + __expf(-gi));
        float sf = 1.f / (1.f + __expf(-gf));
        float so = 1.f / (1.f + __expf(-go));
        float cn = sf * c0[(size_t)b * HDIM + h] + si * tanhf(gg);
        float hn = so * tanhf(cn);
        g_hN[(size_t)b * HDIM + h] = hn;
        out[(size_t)B * VDIM + (size_t)b * HDIM + h] = hn;
        out[(size_t)B * VDIM + (size_t)B * HDIM + (size_t)b * HDIM + h] = cn;
    }
}

// ---------------- host launch (graph-capturable: kernel launches only) ----------------
extern "C" void kernel_launch(void* const* d_in, const int* in_sizes, int n_in,
                              void* d_out, int out_size)
{
    const int*   tokens = (const int*)  d_in[0];
    const float* enc    = (const float*)d_in[1];
    const float* h0     = (const float*)d_in[2];
    const float* c0     = (const float*)d_in[3];
    const float* emb    = (const float*)d_in[4];
    const float* W_in   = (const float*)d_in[5];
    const float* W_out  = (const float*)d_in[6];
    const float* W_ih   = (const float*)d_in[7];
    const float* W_hh   = (const float*)d_in[8];
    const float* b_ih   = (const float*)d_in[9];
    const float* b_hh   = (const float*)d_in[10];
    const float* W_gen  = (const float*)d_in[11];
    const float* b_gen  = (const float*)d_in[12];
    float* out = (float*)d_out;

    float *part, *qbuf, *catA, *catB, *gates, *hN;
    cudaGetSymbolAddress((void**)&part,  g_part);
    cudaGetSymbolAddress((void**)&qbuf,  g_q);
    cudaGetSymbolAddress((void**)&catA,  g_catA);
    cudaGetSymbolAddress((void**)&catB,  g_catB);
    cudaGetSymbolAddress((void**)&gates, g_gates);
    cudaGetSymbolAddress((void**)&hN,    g_hN);

    // embedding gather (independent)
    k_embed<<<B, 128>>>(tokens, emb);

    // q = h0 @ W_in  (W_in is [K=H rows, N=H cols] -> N-major), split-K 16
    k_gemm<false, false><<<dim3(8, 16), 256>>>(h0, HDIM, W_in, HDIM,
                                               part, 0, HDIM, HDIM, 16, 0, nullptr);
    k_scomb<<<(B * HDIM + 255) / 256, 256>>>(part, HDIM, 16, nullptr, nullptr, 0, qbuf, HDIM);

    // fused single-pass attention over encoder_out
    k_attn<<<dim3(8, B), 256>>>(enc);
    k_attn_comb<<<B, 256>>>(h0);

    // ctx_hat = tanh(catA @ W_out^T)  (W_out [N=H, K=2H] K-major), split-K 16
    k_gemm<true, false><<<dim3(8, 16), 256>>>(catA, 2 * HDIM, W_out, 2 * HDIM,
                                              part, 0, HDIM, 2 * HDIM, 16, 0, nullptr);
    k_scomb<<<(B * HDIM + 255) / 256, 256>>>(part, HDIM, 16, nullptr, nullptr, 1, catB, KCAT);

    // gates = catB @ W_ih^T + h0 @ W_hh^T + b_ih + b_hh   (two passes into slices 0..7 / 8..15)
    k_gemm<true, false><<<dim3(32, 8), 256>>>(catB, KCAT, W_ih, KCAT,
                                              part, 0, G4, KCAT, 8, 0, nullptr);
    k_gemm<true, false><<<dim3(32, 8), 256>>>(h0, HDIM, W_hh, HDIM,
                                              part, 0, G4, HDIM, 8, 8, nullptr);
    k_scomb<<<(B * G4 + 255) / 256, 256>>>(part, G4, 16, b_ih, b_hh, 0, gates, G4);

    // LSTM cell -> hN, cN (also written to d_out tail)
    k_lstm<<<B, 256>>>(c0, out);

    // logits = hN @ W_gen^T + b_gen  (direct, no split)
    k_gemm<true, true><<<dim3((VDIM + 127) / 128, 1), 256>>>(hN, HDIM, W_gen, HDIM,
                                                             out, VDIM, VDIM, HDIM, 1, 0, b_gen);
}

// round 2
// speedup vs baseline: 1.7068x; 1.7068x over previous
#include <cuda_runtime.h>
#include <cstdint>

#define B    64
#define HDIM 1024
#define SDIM 2048
#define VDIM 23262
#define EDIM 300
#define G4   4096          // 4*H
#define KCAT (HDIM + EDIM) // 1324

typedef unsigned long long ull;

// ---------------- scratch (static device globals; no allocation) ----------------
__device__ float g_q[B * HDIM];
__device__ float g_pm[B * 64];
__device__ float g_pl[B * 64];
__device__ float g_pacc[(size_t)B * 64 * HDIM];   // 16.8 MB attention partials
__device__ float g_catA[B * 2 * HDIM];            // [context | h0]
__device__ float g_catB[B * KCAT];                // [ctx_hat | embedded]
__device__ float g_gates[B * G4];
__device__ float g_hN[B * HDIM];
__device__ float g_part[(size_t)6 * 1024 * 1024]; // 25 MB split-K partials

// ---------------- packed f32x2 helpers ----------------
__device__ __forceinline__ void ffma2(ull& d, ull a, ull w) {
    asm("fma.rn.f32x2 %0, %1, %2, %0;" : "+l"(d) : "l"(a), "l"(w));
}
__device__ __forceinline__ ull pack_dup(float x) {
    ull r;
    asm("mov.b64 %0, {%1, %1};" : "=l"(r) : "f"(x));
    return r;
}
__device__ __forceinline__ float2 unpack2(ull v) {
    float2 r;
    asm("mov.b64 {%0, %1}, %2;" : "=f"(r.x), "=f"(r.y) : "l"(v));
    return r;
}

// ---------------- embedding gather into catB[:, H:H+E] ----------------
__global__ void k_embed(const int* __restrict__ tokens, const float* __restrict__ emb) {
    int b = blockIdx.x;
    int t = tokens[b];
    for (int e = threadIdx.x; e < EDIM; e += blockDim.x)
        g_catB[b * KCAT + HDIM + e] = emb[(size_t)t * EDIM + e];
}

// ---------------- skinny GEMM: C[b,n] = sum_k A[b,k] * W(n,k) ----------------
// Tile: 128 n x 64 b x 32 k. 256 threads: tx=tid&31 owns n-quad (tx*4..+3),
// ty=tid>>5 (warp) owns b-octet (ty*8..+7). fma.rn.f32x2 inner loop.
// WKMAJOR: W stored [N,K]; else [K,N].
// DIRECT: C[b*ldc+n] += bias. else split-K partial at ((slice_base+by)*64+b)*N+n.
template <bool WKMAJOR, bool DIRECT>
__global__ __launch_bounds__(256) void k_gemm(
    const float* __restrict__ A, int lda,
    const float* __restrict__ W, int ldw,
    float* __restrict__ C, int ldc,
    int N, int K, int nsl, int slice_base,
    const float* __restrict__ bias)
{
    __shared__ float sW[32][128];   // [k][n]
    __shared__ float sA[32][64];    // [k][b]
    int tid = threadIdx.x;
    int tx = tid & 31, ty = tid >> 5;
    int n0 = blockIdx.x * 128;

    int nk32 = (K + 31) >> 5;
    int per  = (nk32 + nsl - 1) / nsl;
    int k0s  = blockIdx.y * per * 32;
    int k0e  = min(K, (int)(blockIdx.y + 1) * per * 32);

    ull acc[8][2];
#pragma unroll
    for (int j = 0; j < 8; j++) { acc[j][0] = 0ULL; acc[j][1] = 0ULL; }

    for (int k0 = k0s; k0 < k0e; k0 += 32) {
        bool full = (k0 + 32 <= K);
        // --- A tile: thread loads 2 float4 along k, scatters to sA[k][b] ---
        {
            int bb = tid >> 2;
            int kq = (tid & 3) * 4;
            const float* ap = A + (size_t)bb * lda + k0;
#pragma unroll
            for (int c = 0; c < 2; c++) {
                int off = kq + c * 16;
                float4 v;
                if (full) {
                    v = *(const float4*)(ap + off);
                } else {
                    v.x = (k0 + off + 0 < K) ? ap[off + 0] : 0.f;
                    v.y = (k0 + off + 1 < K) ? ap[off + 1] : 0.f;
                    v.z = (k0 + off + 2 < K) ? ap[off + 2] : 0.f;
                    v.w = (k0 + off + 3 < K) ? ap[off + 3] : 0.f;
                }
                sA[off + 0][bb] = v.x;
                sA[off + 1][bb] = v.y;
                sA[off + 2][bb] = v.z;
                sA[off + 3][bb] = v.w;
            }
        }
        // --- W tile ---
        if (WKMAJOR) {
            // thread: n = tid>>1 (0..127), k-half = (tid&1)*16, 4 float4 along k
            int n    = tid >> 1;
            int half = (tid & 1) * 16;
            bool nv  = (n0 + n) < N;
            const float* wp = W + (size_t)(n0 + n) * ldw + k0 + half;
#pragma unroll
            for (int c = 0; c < 4; c++) {
                int off = half + c * 4;
                float4 v;
                if (nv && full) {
                    v = *(const float4*)(wp + c * 4);
                } else {
                    v.x = (nv && k0 + off + 0 < K) ? wp[c * 4 + 0] : 0.f;
                    v.y = (nv && k0 + off + 1 < K) ? wp[c * 4 + 1] : 0.f;
                    v.z = (nv && k0 + off + 2 < K) ? wp[c * 4 + 2] : 0.f;
                    v.w = (nv && k0 + off + 3 < K) ? wp[c * 4 + 3] : 0.f;
                }
                sW[off + 0][n] = v.x;
                sW[off + 1][n] = v.y;
                sW[off + 2][n] = v.z;
                sW[off + 3][n] = v.w;
            }
        } else {
            // [K,N]: thread: kk = tid>>3, n-off = (tid&7)*4 + c*32, contiguous stores
            int kk = tid >> 3;
            int k  = k0 + kk;
            bool kv = k < K;
            const float* wp = W + (size_t)k * ldw + n0;
#pragma unroll
            for (int c = 0; c < 4; c++) {
                int nn = (tid & 7) * 4 + c * 32;
                float4 v;
                if (kv && (n0 + nn + 3) < N) {
                    v = *(const float4*)(wp + nn);
                } else {
                    v.x = (kv && n0 + nn + 0 < N) ? wp[nn + 0] : 0.f;
                    v.y = (kv && n0 + nn + 1 < N) ? wp[nn + 1] : 0.f;
                    v.z = (kv && n0 + nn + 2 < N) ? wp[nn + 2] : 0.f;
                    v.w = (kv && n0 + nn + 3 < N) ? wp[nn + 3] : 0.f;
                }
                *(float4*)&sW[kk][nn] = v;
            }
        }
        __syncthreads();

#pragma unroll 8
        for (int kk = 0; kk < 32; kk++) {
            float4 a0 = *(const float4*)&sA[kk][ty * 8];
            float4 a1 = *(const float4*)&sA[kk][ty * 8 + 4];
            const ull* wp2 = (const ull*)&sW[kk][tx * 4];
            ull w0 = wp2[0], w1 = wp2[1];
            ull ad[8];
            ad[0] = pack_dup(a0.x); ad[1] = pack_dup(a0.y);
            ad[2] = pack_dup(a0.z); ad[3] = pack_dup(a0.w);
            ad[4] = pack_dup(a1.x); ad[5] = pack_dup(a1.y);
            ad[6] = pack_dup(a1.z); ad[7] = pack_dup(a1.w);
#pragma unroll
            for (int j = 0; j < 8; j++) {
                ffma2(acc[j][0], ad[j], w0);
                ffma2(acc[j][1], ad[j], w1);
            }
        }
        __syncthreads();
    }

    // --- epilogue ---
#pragma unroll
    for (int j = 0; j < 8; j++) {
        int bb = ty * 8 + j;
#pragma unroll
        for (int p = 0; p < 2; p++) {
            float2 v = unpack2(acc[j][p]);
            int n = n0 + tx * 4 + p * 2;
            if (DIRECT) {
                if (bias) { v.x += bias[n]; if (n + 1 < N) v.y += bias[n + 1]; }
                if (n + 1 < N)      *(float2*)&C[(size_t)bb * ldc + n] = v;
                else if (n < N)     C[(size_t)bb * ldc + n] = v.x;
            } else {
                size_t base = ((size_t)(slice_base + blockIdx.y) * B + bb) * (size_t)N;
                if (n + 1 < N)      *(float2*)&C[base + n] = v;
                else if (n < N)     C[base + n] = v.x;
            }
        }
    }
}

// ---------------- split-K combine (+bias, +optional tanh) ----------------
__global__ void k_scomb(const float* __restrict__ part, int N, int nsl,
                        const float* __restrict__ b1, const float* __restrict__ b2,
                        int act, float* __restrict__ dst, int ldd)
{
    int idx = blockIdx.x * blockDim.x + threadIdx.x;
    if (idx >= B * N) return;
    int b = idx / N, n = idx % N;
    float v = 0.f;
    if (b1) v += b1[n];
    if (b2) v += b2[n];
    for (int s = 0; s < nsl; s++) v += part[((size_t)s * B + b) * (size_t)N + n];
    if (act) v = tanhf(v);
    dst[(size_t)b * ldd + n] = v;
}

// ---------------- fused attention pass (single read of encoder_out) ----------------
__global__ __launch_bounds__(256) void k_attn(const float* __restrict__ enc)
{
    int b = blockIdx.y;
    int warp = threadIdx.x >> 5, lane = threadIdx.x & 31;
    int wg = blockIdx.x * 8 + warp;   // 0..63

    const float4* qp = (const float4*)(g_q + (size_t)b * HDIM);
    float4 qv[8];
#pragma unroll
    for (int j = 0; j < 8; j++) qv[j] = qp[j * 32 + lane];

    float4 av[8];
#pragma unroll
    for (int j = 0; j < 8; j++) av[j] = make_float4(0.f, 0.f, 0.f, 0.f);
    float m = -1e30f, l = 0.f;

    int s0 = wg * 32;
    for (int r = 0; r < 32; r++) {
        const float4* row = (const float4*)(enc + ((size_t)(s0 + r) * B + b) * HDIM);
        float4 e[8];
#pragma unroll
        for (int j = 0; j < 8; j++) e[j] = row[j * 32 + lane];
        float d = 0.f;
#pragma unroll
        for (int j = 0; j < 8; j++)
            d += e[j].x * qv[j].x + e[j].y * qv[j].y + e[j].z * qv[j].z + e[j].w * qv[j].w;
#pragma unroll
        for (int off = 16; off > 0; off >>= 1)
            d += __shfl_xor_sync(0xffffffffu, d, off);

        float mn  = fmaxf(m, d);
        float fac = __expf(m - mn);
        float p   = __expf(d - mn);
        l = l * fac + p;
        m = mn;
#pragma unroll
        for (int j = 0; j < 8; j++) {
            av[j].x = av[j].x * fac + p * e[j].x;
            av[j].y = av[j].y * fac + p * e[j].y;
            av[j].z = av[j].z * fac + p * e[j].z;
            av[j].w = av[j].w * fac + p * e[j].w;
        }
    }
    int pi = b * 64 + wg;
    if (lane == 0) { g_pm[pi] = m; g_pl[pi] = l; }
    float4* pa = (float4*)(g_pacc + (size_t)pi * HDIM);
#pragma unroll
    for (int j = 0; j < 8; j++) pa[j * 32 + lane] = av[j];
}

// ---------------- attention combine: context -> catA = [context | h0] ----------------
__global__ void k_attn_comb(const float* __restrict__ h0)
{
    int b = blockIdx.x, t = threadIdx.x;   // 256 threads, 4 h each
    float M = -1e30f;
    for (int c = 0; c < 64; c++) M = fmaxf(M, g_pm[b * 64 + c]);
    float lsum = 0.f;
    float4 ctx = make_float4(0.f, 0.f, 0.f, 0.f);
    for (int c = 0; c < 64; c++) {
        float fac = __expf(g_pm[b * 64 + c] - M);
        lsum += fac * g_pl[b * 64 + c];
        float4 a = *(const float4*)(g_pacc + (size_t)(b * 64 + c) * HDIM + t * 4);
        ctx.x += fac * a.x; ctx.y += fac * a.y;
        ctx.z += fac * a.z; ctx.w += fac * a.w;
    }
    float inv = 1.f / lsum;
    float4* dA = (float4*)(g_catA + (size_t)b * 2 * HDIM);
    dA[t] = make_float4(ctx.x * inv, ctx.y * inv, ctx.z * inv, ctx.w * inv);
    const float4* h4 = (const float4*)(h0 + (size_t)b * HDIM);
    dA[256 + t] = h4[t];
}

// ---------------- LSTM elementwise; writes hN/cN into d_out and g_hN ----------------
__global__ void k_lstm(const float* __restrict__ c0, float* __restrict__ out)
{
    int b = blockIdx.x, t = threadIdx.x;
    const float* g = g_gates + (size_t)b * G4;
#pragma unroll
    for (int c = 0; c < 4; c++) {
        int h = t * 4 + c;
        float gi = g[h], gf = g[HDIM + h], gg = g[2 * HDIM + h], go = g[3 * HDIM + h];
        float si = 1.f / (1.f + __expf(-gi));
        float sf = 1.f / (1.f + __expf(-gf));
        float so = 1.f / (1.f + __expf(-go));
        float cn = sf * c0[(size_t)b * HDIM + h] + si * tanhf(gg);
        float hn = so * tanhf(cn);
        g_hN[(size_t)b * HDIM + h] = hn;
        out[(size_t)B * VDIM + (size_t)b * HDIM + h] = hn;
        out[(size_t)B * VDIM + (size_t)B * HDIM + (size_t)b * HDIM + h] = cn;
    }
}

// ---------------- host launch (graph-capturable: kernel launches only) ----------------
extern "C" void kernel_launch(void* const* d_in, const int* in_sizes, int n_in,
                              void* d_out, int out_size)
{
    const int*   tokens = (const int*)  d_in[0];
    const float* enc    = (const float*)d_in[1];
    const float* h0     = (const float*)d_in[2];
    const float* c0     = (const float*)d_in[3];
    const float* emb    = (const float*)d_in[4];
    const float* W_in   = (const float*)d_in[5];
    const float* W_out  = (const float*)d_in[6];
    const float* W_ih   = (const float*)d_in[7];
    const float* W_hh   = (const float*)d_in[8];
    const float* b_ih   = (const float*)d_in[9];
    const float* b_hh   = (const float*)d_in[10];
    const float* W_gen  = (const float*)d_in[11];
    const float* b_gen  = (const float*)d_in[12];
    float* out = (float*)d_out;

    float *part, *qbuf, *catA, *catB, *gates, *hN;
    cudaGetSymbolAddress((void**)&part,  g_part);
    cudaGetSymbolAddress((void**)&qbuf,  g_q);
    cudaGetSymbolAddress((void**)&catA,  g_catA);
    cudaGetSymbolAddress((void**)&catB,  g_catB);
    cudaGetSymbolAddress((void**)&gates, g_gates);
    cudaGetSymbolAddress((void**)&hN,    g_hN);

    // embedding gather (independent)
    k_embed<<<B, 128>>>(tokens, emb);

    // q = h0 @ W_in  (W_in [K=H, N=H] n-major), split-K 16
    k_gemm<false, false><<<dim3(8, 16), 256>>>(h0, HDIM, W_in, HDIM,
                                               part, 0, HDIM, HDIM, 16, 0, nullptr);
    k_scomb<<<(B * HDIM + 255) / 256, 256>>>(part, HDIM, 16, nullptr, nullptr, 0, qbuf, HDIM);

    // fused single-pass attention over encoder_out
    k_attn<<<dim3(8, B), 256>>>(enc);
    k_attn_comb<<<B, 256>>>(h0);

    // ctx_hat = tanh(catA @ W_out^T)  (W_out [N=H, K=2H] k-major), split-K 16
    k_gemm<true, false><<<dim3(8, 16), 256>>>(catA, 2 * HDIM, W_out, 2 * HDIM,
                                              part, 0, HDIM, 2 * HDIM, 16, 0, nullptr);
    k_scomb<<<(B * HDIM + 255) / 256, 256>>>(part, HDIM, 16, nullptr, nullptr, 1, catB, KCAT);

    // gates = catB @ W_ih^T + h0 @ W_hh^T + biases (slices 0..7 / 8..15)
    k_gemm<true, false><<<dim3(32, 8), 256>>>(catB, KCAT, W_ih, KCAT,
                                              part, 0, G4, KCAT, 8, 0, nullptr);
    k_gemm<true, false><<<dim3(32, 8), 256>>>(h0, HDIM, W_hh, HDIM,
                                              part, 0, G4, HDIM, 8, 8, nullptr);
    k_scomb<<<(B * G4 + 255) / 256, 256>>>(part, G4, 16, b_ih, b_hh, 0, gates, G4);

    // LSTM cell -> hN, cN (also written to d_out tail)
    k_lstm<<<B, 256>>>(c0, out);

    // logits = hN @ W_gen^T + b_gen, split-K 4 to balance waves, then combine
    k_gemm<true, false><<<dim3((VDIM + 127) / 128, 4), 256>>>(hN, HDIM, W_gen, HDIM,
                                                              part, 0, VDIM, HDIM, 4, 0, nullptr);
    k_scomb<<<(B * VDIM + 255) / 256, 256>>>(part, VDIM, 4, b_gen, nullptr, 0, out, VDIM);
}